// round 15
// baseline (speedup 1.0000x reference)
#include <cuda_runtime.h>

#define T_SEQ 2048
#define B_SZ  512
#define NTICK (T_SEQ / 4 + 2)   // 4 timesteps per tick + 2 pipeline fill

// h1 scratch for the deferred dense head (134 MB)
__device__ __align__(16) float g_h1[(size_t)T_SEQ * B_SZ * 32];

typedef unsigned long long u64;

// ---------- packed f32x2 helpers ----------
__device__ __forceinline__ u64 pack2(float a, float b) {
    u64 d; asm("mov.b64 %0,{%1,%2};" : "=l"(d) : "f"(a), "f"(b)); return d;
}
__device__ __forceinline__ void unpack2(u64 v, float& a, float& b) {
    asm("mov.b64 {%0,%1},%2;" : "=f"(a), "=f"(b) : "l"(v));
}
__device__ __forceinline__ u64 fma2(u64 a, u64 b, u64 c) {
    u64 d; asm("fma.rn.f32x2 %0,%1,%2,%3;" : "=l"(d) : "l"(a), "l"(b), "l"(c)); return d;
}
__device__ __forceinline__ u64 add2(u64 a, u64 b) {
    u64 d; asm("add.rn.f32x2 %0,%1,%2;" : "=l"(d) : "l"(a), "l"(b)); return d;
}

// ---------- activations via HW MUFU tanh (validated R6-R14, err ~5e-6) ----------
// i/f/o gate pre-activations arrive PRE-SCALED by 0.5 (folded into weights),
// so sigmoid(x) = 0.5 + 0.5*tanh(x/2) needs no pre-multiply here.
__device__ __forceinline__ float htanh(float x) {
    float y; asm("tanh.approx.f32 %0,%1;" : "=f"(y) : "f"(x)); return y;
}
__device__ __forceinline__ float tanhf_(float x){ return htanh(x); }

// Gate-pair matvec: two half-chains (k 0..15 / 16..31) per accumulator,
// combined with one add2 -> 4 independent 16-deep chains (validated R11).
__device__ __forceinline__ void matvec(const ulonglong2* __restrict__ hv,
                                       const u64* __restrict__ w_if,
                                       const u64* __restrict__ w_go,
                                       u64 if0, u64 go0, u64& aif, u64& ago)
{
    u64 aL = if0, gL = go0, aH = 0ull, gH = 0ull;
#pragma unroll
    for (int m = 0; m < 8; m++) {
        ulonglong2 h2 = hv[m];
        aL = fma2(h2.x, w_if[2*m],   aL);
        gL = fma2(h2.x, w_go[2*m],   gL);
        aL = fma2(h2.y, w_if[2*m+1], aL);
        gL = fma2(h2.y, w_go[2*m+1], gL);
    }
#pragma unroll
    for (int m = 8; m < 16; m++) {
        ulonglong2 h2 = hv[m];
        aH = fma2(h2.x, w_if[2*m],   aH);
        gH = fma2(h2.x, w_go[2*m],   gH);
        aH = fma2(h2.y, w_if[2*m+1], aH);
        gH = fma2(h2.y, w_go[2*m+1], gH);
    }
    aif = add2(aL, aH);
    ago = add2(gL, gH);
}

// i/f/o pre-scaled by 0.5; g unscaled.
__device__ __forceinline__ float cellstep(u64 aif, u64 ago, float& c) {
    float gi, gf, gg, go;
    unpack2(aif, gi, gf); unpack2(ago, gg, go);
    gi = fmaf(htanh(gi), 0.5f, 0.5f);
    gf = fmaf(htanh(gf), 0.5f, 0.5f);
    gg = htanh(gg);
    go = fmaf(htanh(go), 0.5f, 0.5f);
    c = gf * c + gi * gg;
    return go * tanhf_(c);
}

// =====================================================================
// Fused 2-layer LSTM. Block = 4 trios = 12 warps (384 threads), 4 steps
// per tick (R13 machinery). KEY FIX: warp->SMSP is wid%4 WITHIN the
// block, so 96-thread blocks never used SMSP3 (3-SMSP pipe floor = 768
// cyc/step — exactly the measured 775). 384-thread blocks cover all 4
// SMSPs: with e=wid/3, role=wid%3 every SMSP gets exactly 3 warps, one
// of each role, from different trios -> floor 576 cyc/step.
//   role 0: layer-0 cell       (h0[4m..4m+3] at tick m)
//   role 1: layer-1 input proj (xp1 of tick m-1; 4 independent matvecs)
//   role 2: layer-1 cell       (h1 of tick m-2)
// i/f/o sigmoid pre-scale 0.5 folded into weights/biases (shorter tail).
// grid = 128 blocks x 384 threads, 1 block/SM.
// =====================================================================
__global__ void __launch_bounds__(384, 1)
k_fused(const float* __restrict__ x,
        const float* __restrict__ Wih0, const float* __restrict__ Whh0,
        const float* __restrict__ bih0, const float* __restrict__ bhh0,
        const float* __restrict__ Wih1, const float* __restrict__ Whh1,
        const float* __restrict__ bih1, const float* __restrict__ bhh1)
{
    __shared__ __align__(16) float      h0ring[4][2][4][64];  // [e][slot][step] {h,h} pairs
    __shared__ __align__(16) ulonglong2 pring[4][2][4][32];   // [e][slot][step][j]={aif,ago}
    __shared__ __align__(16) float      h1ring[4][2][4][64];

    const int tid  = threadIdx.x;
    const int wid  = tid >> 5, j = tid & 31;
    const int e    = wid / 3;              // trio (0..3)
    const int role = wid - 3 * e;          // 0=L0 cell, 1=proj, 2=L1 cell
    const int b    = blockIdx.x * 4 + e;

    // zero initial hidden states (all ring slots)
    for (int i = tid; i < 4 * 2 * 4 * 64; i += 384) {
        ((float*)h0ring)[i] = 0.f;
        ((float*)h1ring)[i] = 0.f;
    }

    // per-role weight matrix -> 64 u64 regs of gate-pair columns.
    // 0.5 sigmoid pre-scale folded into i, f, o rows (g row unscaled).
    const float* Wsrc = (role == 0) ? Whh0 : (role == 1) ? Wih1 : Whh1;
    u64 w_if[32], w_go[32];
#pragma unroll
    for (int k = 0; k < 32; k++) {
        w_if[k] = pack2(0.5f * Wsrc[j * 32 + k],  0.5f * Wsrc[(32 + j) * 32 + k]);
        w_go[k] = pack2(Wsrc[(64 + j) * 32 + k],  0.5f * Wsrc[(96 + j) * 32 + k]);
    }

    u64 wx_if = 0, wx_go = 0, bs_if = 0, bs_go = 0;
    if (role == 0) {
        wx_if = pack2(0.5f * Wih0[j],      0.5f * Wih0[32 + j]);
        wx_go = pack2(Wih0[64 + j],        0.5f * Wih0[96 + j]);
        bs_if = pack2(0.5f * (bih0[j] + bhh0[j]),
                      0.5f * (bih0[32 + j] + bhh0[32 + j]));
        bs_go = pack2((bih0[64 + j] + bhh0[64 + j]),
                      0.5f * (bih0[96 + j] + bhh0[96 + j]));
    } else if (role == 1) {
        bs_if = pack2(0.5f * (bih1[j] + bhh1[j]),
                      0.5f * (bih1[32 + j] + bhh1[32 + j]));
        bs_go = pack2((bih1[64 + j] + bhh1[64 + j]),
                      0.5f * (bih1[96 + j] + bhh1[96 + j]));
    }

    float c = 0.f;                     // cell state (roles 0 and 2)
    float xt0 = x[b];                  // x[0..3]  (IN == 1)
    float xt1 = x[1 * B_SZ + b];
    float xt2 = x[2 * B_SZ + b];
    float xt3 = x[3 * B_SZ + b];

    __syncthreads();                   // init visible

#pragma unroll 1
    for (int n = 0; n < NTICK; n++) {
        if (role == 0) {
            if (n < T_SEQ / 4) {
                const int t0 = 4 * n;
                const int p0 = (t0 + 4 < T_SEQ) ? (t0 + 4) : (T_SEQ - 1);
                const int p1 = (t0 + 5 < T_SEQ) ? (t0 + 5) : (T_SEQ - 1);
                const int p2 = (t0 + 6 < T_SEQ) ? (t0 + 6) : (T_SEQ - 1);
                const int p3 = (t0 + 7 < T_SEQ) ? (t0 + 7) : (T_SEQ - 1);
                float xn0 = x[p0 * B_SZ + b], xn1 = x[p1 * B_SZ + b];
                float xn2 = x[p2 * B_SZ + b], xn3 = x[p3 * B_SZ + b];
                const int s = n & 1;
                u64 aif, ago;
                // step 0: from prev tick's step 3
                matvec(reinterpret_cast<const ulonglong2*>(h0ring[e][s ^ 1][3]),
                       w_if, w_go,
                       fma2(pack2(xt0, xt0), wx_if, bs_if),
                       fma2(pack2(xt0, xt0), wx_go, bs_go), aif, ago);
                float h = cellstep(aif, ago, c);
                reinterpret_cast<u64*>(h0ring[e][s][0])[j] = pack2(h, h);
                __syncwarp();
                // step 1
                matvec(reinterpret_cast<const ulonglong2*>(h0ring[e][s][0]),
                       w_if, w_go,
                       fma2(pack2(xt1, xt1), wx_if, bs_if),
                       fma2(pack2(xt1, xt1), wx_go, bs_go), aif, ago);
                h = cellstep(aif, ago, c);
                reinterpret_cast<u64*>(h0ring[e][s][1])[j] = pack2(h, h);
                __syncwarp();
                // step 2
                matvec(reinterpret_cast<const ulonglong2*>(h0ring[e][s][1]),
                       w_if, w_go,
                       fma2(pack2(xt2, xt2), wx_if, bs_if),
                       fma2(pack2(xt2, xt2), wx_go, bs_go), aif, ago);
                h = cellstep(aif, ago, c);
                reinterpret_cast<u64*>(h0ring[e][s][2])[j] = pack2(h, h);
                __syncwarp();
                // step 3
                matvec(reinterpret_cast<const ulonglong2*>(h0ring[e][s][2]),
                       w_if, w_go,
                       fma2(pack2(xt3, xt3), wx_if, bs_if),
                       fma2(pack2(xt3, xt3), wx_go, bs_go), aif, ago);
                h = cellstep(aif, ago, c);
                reinterpret_cast<u64*>(h0ring[e][s][3])[j] = pack2(h, h);
                xt0 = xn0; xt1 = xn1; xt2 = xn2; xt3 = xn3;
            }
        } else if (role == 1) {
            if (n >= 1 && n <= T_SEQ / 4) {
                const int s = (n - 1) & 1;
                {
                    u64 aifA, agoA, aifB, agoB;
                    matvec(reinterpret_cast<const ulonglong2*>(h0ring[e][s][0]),
                           w_if, w_go, bs_if, bs_go, aifA, agoA);
                    matvec(reinterpret_cast<const ulonglong2*>(h0ring[e][s][1]),
                           w_if, w_go, bs_if, bs_go, aifB, agoB);
                    pring[e][s][0][j] = make_ulonglong2(aifA, agoA);   // STS.128
                    pring[e][s][1][j] = make_ulonglong2(aifB, agoB);
                }
                {
                    u64 aifA, agoA, aifB, agoB;
                    matvec(reinterpret_cast<const ulonglong2*>(h0ring[e][s][2]),
                           w_if, w_go, bs_if, bs_go, aifA, agoA);
                    matvec(reinterpret_cast<const ulonglong2*>(h0ring[e][s][3]),
                           w_if, w_go, bs_if, bs_go, aifB, agoB);
                    pring[e][s][2][j] = make_ulonglong2(aifA, agoA);
                    pring[e][s][3][j] = make_ulonglong2(aifB, agoB);
                }
            }
        } else {
            if (n >= 2) {
                const int t0 = 4 * (n - 2);
                const int s  = n & 1;                  // slot (n-2)&1 == n&1
                float* h1o = g_h1 + (size_t)t0 * (B_SZ * 32) + b * 32 + j;
                u64 aif, ago;
                // step 0: from prev tick's step 3
                ulonglong2 p0v = pring[e][s][0][j];    // LDS.128
                matvec(reinterpret_cast<const ulonglong2*>(h1ring[e][s ^ 1][3]),
                       w_if, w_go, p0v.x, p0v.y, aif, ago);
                float h = cellstep(aif, ago, c);
                reinterpret_cast<u64*>(h1ring[e][s][0])[j] = pack2(h, h);
                h1o[0] = h;
                __syncwarp();
                // step 1
                ulonglong2 p1v = pring[e][s][1][j];
                matvec(reinterpret_cast<const ulonglong2*>(h1ring[e][s][0]),
                       w_if, w_go, p1v.x, p1v.y, aif, ago);
                h = cellstep(aif, ago, c);
                reinterpret_cast<u64*>(h1ring[e][s][1])[j] = pack2(h, h);
                h1o[B_SZ * 32] = h;
                __syncwarp();
                // step 2
                ulonglong2 p2v = pring[e][s][2][j];
                matvec(reinterpret_cast<const ulonglong2*>(h1ring[e][s][1]),
                       w_if, w_go, p2v.x, p2v.y, aif, ago);
                h = cellstep(aif, ago, c);
                reinterpret_cast<u64*>(h1ring[e][s][2])[j] = pack2(h, h);
                h1o[2 * B_SZ * 32] = h;
                __syncwarp();
                // step 3
                ulonglong2 p3v = pring[e][s][3][j];
                matvec(reinterpret_cast<const ulonglong2*>(h1ring[e][s][2]),
                       w_if, w_go, p3v.x, p3v.y, aif, ago);
                h = cellstep(aif, ago, c);
                reinterpret_cast<u64*>(h1ring[e][s][3])[j] = pack2(h, h);
                h1o[3 * B_SZ * 32] = h;
            }
        }
        __syncthreads();               // one block barrier per 4 timesteps
    }
}

// =====================================================================
// Dense head: out[t,b] = sum_j h1[t,b,j]*Wd[j] + bd. Memory-bound (~30us).
// =====================================================================
__global__ void __launch_bounds__(256)
k_head(const float* __restrict__ Wd, const float* __restrict__ bd,
       float* __restrict__ out)
{
    const int gw = blockIdx.x * 8 + (threadIdx.x >> 5);
    const int j  = threadIdx.x & 31;
    const size_t r = (size_t)gw * 4 + (j >> 3);
    const int q  = j & 7;

    float4 h = reinterpret_cast<const float4*>(g_h1)[r * 8 + q];
    float4 w = reinterpret_cast<const float4*>(Wd)[q];
    float s = h.x * w.x + h.y * w.y + h.z * w.z + h.w * w.w;
    s += __shfl_xor_sync(0xffffffffu, s, 1);
    s += __shfl_xor_sync(0xffffffffu, s, 2);
    s += __shfl_xor_sync(0xffffffffu, s, 4);
    if (q == 0) out[r] = s + bd[0];
}

// =====================================================================
extern "C" void kernel_launch(void* const* d_in, const int* in_sizes, int n_in,
                              void* d_out, int out_size)
{
    const float* x    = (const float*)d_in[0];
    const float* Wih0 = (const float*)d_in[1];
    const float* Whh0 = (const float*)d_in[2];
    const float* bih0 = (const float*)d_in[3];
    const float* bhh0 = (const float*)d_in[4];
    const float* Wih1 = (const float*)d_in[5];
    const float* Whh1 = (const float*)d_in[6];
    const float* bih1 = (const float*)d_in[7];
    const float* bhh1 = (const float*)d_in[8];
    const float* Wd   = (const float*)d_in[9];
    const float* bd   = (const float*)d_in[10];

    k_fused<<<128, 384>>>(x, Wih0, Whh0, bih0, bhh0, Wih1, Whh1, bih1, bhh1);
    k_head<<<32768, 256>>>(Wd, bd, (float*)d_out);
}

// round 16
// speedup vs baseline: 1.1867x; 1.1867x over previous
#include <cuda_runtime.h>

#define T_SEQ 2048
#define B_SZ  512
#define NTICK (T_SEQ / 4 + 2)   // 4 timesteps per tick + 2 pipeline fill

// h1 scratch for the deferred dense head (134 MB)
__device__ __align__(16) float g_h1[(size_t)T_SEQ * B_SZ * 32];

typedef unsigned long long u64;

// ---------- packed f32x2 helpers ----------
__device__ __forceinline__ u64 pack2(float a, float b) {
    u64 d; asm("mov.b64 %0,{%1,%2};" : "=l"(d) : "f"(a), "f"(b)); return d;
}
__device__ __forceinline__ void unpack2(u64 v, float& a, float& b) {
    asm("mov.b64 {%0,%1},%2;" : "=f"(a), "=f"(b) : "l"(v));
}
__device__ __forceinline__ u64 fma2(u64 a, u64 b, u64 c) {
    u64 d; asm("fma.rn.f32x2 %0,%1,%2,%3;" : "=l"(d) : "l"(a), "l"(b), "l"(c)); return d;
}

// ---------- activations via HW MUFU tanh (validated R6-R15, err ~5e-6) ----------
// i/f/o pre-activations arrive PRE-SCALED by 0.5 (folded into weights/biases).
__device__ __forceinline__ float htanh(float x) {
    float y; asm("tanh.approx.f32 %0,%1;" : "=f"(y) : "f"(x)); return y;
}

// Even/odd-pair matvec with BROADCAST h loads:
// h stored as plain 32 floats; ALL lanes read the same float4 address
// (ulonglong2 view) -> broadcast, N=1, ~1 crossbar cyc per LDS.128
// (vs 4 for the old per-lane duplicated {h,h} loads; the old layout made
// the kernel smem-crossbar-bound at ~780 cyc/SM/step).
// Each gate accumulates {sum over even k, sum over odd k}; 4 independent
// 16-deep fma2 chains; final gate = lo + hi + extra.
__device__ __forceinline__ void matvec4(const ulonglong2* __restrict__ hv,
                                        const u64* __restrict__ wI,
                                        const u64* __restrict__ wF,
                                        const u64* __restrict__ wG,
                                        const u64* __restrict__ wO,
                                        u64& aI, u64& aF, u64& aG, u64& aO)
{
    aI = 0ull; aF = 0ull; aG = 0ull; aO = 0ull;
#pragma unroll
    for (int m = 0; m < 8; m++) {
        ulonglong2 hp = hv[m];              // {h4m,h4m+1},{h4m+2,h4m+3} broadcast
        aI = fma2(hp.x, wI[2*m],   aI);
        aF = fma2(hp.x, wF[2*m],   aF);
        aG = fma2(hp.x, wG[2*m],   aG);
        aO = fma2(hp.x, wO[2*m],   aO);
        aI = fma2(hp.y, wI[2*m+1], aI);
        aF = fma2(hp.y, wF[2*m+1], aF);
        aG = fma2(hp.y, wG[2*m+1], aG);
        aO = fma2(hp.y, wO[2*m+1], aO);
    }
}

__device__ __forceinline__ float comb(u64 a, float extra) {
    float lo, hi; unpack2(a, lo, hi); return lo + hi + extra;
}

// i/f/o pre-scaled by 0.5; g unscaled.
__device__ __forceinline__ float cellstep4(float pI, float pF, float pG, float pO,
                                           float& c)
{
    float gi = fmaf(htanh(pI), 0.5f, 0.5f);
    float gf = fmaf(htanh(pF), 0.5f, 0.5f);
    float gg = htanh(pG);
    float go = fmaf(htanh(pO), 0.5f, 0.5f);
    c = gf * c + gi * gg;
    return go * htanh(c);
}

// =====================================================================
// Fused 2-layer LSTM. Block = 4 trios = 12 warps (384 threads), 4 steps
// per barrier tick (R13 machinery), even/odd BROADCAST data layout:
//   role 0: layer-0 cell       (h0[4m..4m+3] at tick m)
//   role 1: layer-1 input proj (xp1 of tick m-1; 4 independent matvecs)
//   role 2: layer-1 cell       (h1 of tick m-2)
// e = wid/3, role = wid%3 -> every SMSP (wid%4) gets one warp of each
// role from different trios; with the crossbar unbound this finally
// exposes the 4-SMSP issue floor.
// grid = 128 blocks x 384 threads, 1 block/SM.
// =====================================================================
__global__ void __launch_bounds__(384, 1)
k_fused(const float* __restrict__ x,
        const float* __restrict__ Wih0, const float* __restrict__ Whh0,
        const float* __restrict__ bih0, const float* __restrict__ bhh0,
        const float* __restrict__ Wih1, const float* __restrict__ Whh1,
        const float* __restrict__ bih1, const float* __restrict__ bhh1)
{
    __shared__ __align__(16) float  h0ring[4][2][4][32];   // [e][slot][step] plain h
    __shared__ __align__(16) float4 pring[4][2][4][32];    // [e][slot][step][j]={i,f,g,o}
    __shared__ __align__(16) float  h1ring[4][2][4][32];

    const int tid  = threadIdx.x;
    const int wid  = tid >> 5, j = tid & 31;
    const int e    = wid / 3;              // trio (0..3)
    const int role = wid - 3 * e;          // 0=L0 cell, 1=proj, 2=L1 cell
    const int b    = blockIdx.x * 4 + e;

    // zero initial hidden states (all ring slots)
    for (int i = tid; i < 4 * 2 * 4 * 32; i += 384) {
        ((float*)h0ring)[i] = 0.f;
        ((float*)h1ring)[i] = 0.f;
    }

    // per-role weight matrix -> 4 gate rows x 16 even/odd u64 pairs.
    // 0.5 sigmoid fold on i, f, o rows; g row unscaled.
    const float* Wsrc = (role == 0) ? Whh0 : (role == 1) ? Wih1 : Whh1;
    u64 wI[16], wF[16], wG[16], wO[16];
#pragma unroll
    for (int p = 0; p < 16; p++) {
        wI[p] = pack2(0.5f * Wsrc[j * 32 + 2*p],        0.5f * Wsrc[j * 32 + 2*p + 1]);
        wF[p] = pack2(0.5f * Wsrc[(32 + j) * 32 + 2*p], 0.5f * Wsrc[(32 + j) * 32 + 2*p + 1]);
        wG[p] = pack2(Wsrc[(64 + j) * 32 + 2*p],        Wsrc[(64 + j) * 32 + 2*p + 1]);
        wO[p] = pack2(0.5f * Wsrc[(96 + j) * 32 + 2*p], 0.5f * Wsrc[(96 + j) * 32 + 2*p + 1]);
    }

    float wxI = 0.f, wxF = 0.f, wxG = 0.f, wxO = 0.f;
    float bI = 0.f, bF = 0.f, bG = 0.f, bO = 0.f;
    if (role == 0) {
        wxI = 0.5f * Wih0[j];       wxF = 0.5f * Wih0[32 + j];
        wxG = Wih0[64 + j];         wxO = 0.5f * Wih0[96 + j];
        bI  = 0.5f * (bih0[j] + bhh0[j]);
        bF  = 0.5f * (bih0[32 + j] + bhh0[32 + j]);
        bG  = (bih0[64 + j] + bhh0[64 + j]);
        bO  = 0.5f * (bih0[96 + j] + bhh0[96 + j]);
    } else if (role == 1) {
        bI  = 0.5f * (bih1[j] + bhh1[j]);
        bF  = 0.5f * (bih1[32 + j] + bhh1[32 + j]);
        bG  = (bih1[64 + j] + bhh1[64 + j]);
        bO  = 0.5f * (bih1[96 + j] + bhh1[96 + j]);
    }

    float c = 0.f;                     // cell state (roles 0 and 2)
    float xt0 = x[b];                  // x[0..3]  (IN == 1)
    float xt1 = x[1 * B_SZ + b];
    float xt2 = x[2 * B_SZ + b];
    float xt3 = x[3 * B_SZ + b];

    __syncthreads();                   // init visible

#pragma unroll 1
    for (int n = 0; n < NTICK; n++) {
        if (role == 0) {
            if (n < T_SEQ / 4) {
                const int t0 = 4 * n;
                const int p0 = (t0 + 4 < T_SEQ) ? (t0 + 4) : (T_SEQ - 1);
                const int p1 = (t0 + 5 < T_SEQ) ? (t0 + 5) : (T_SEQ - 1);
                const int p2 = (t0 + 6 < T_SEQ) ? (t0 + 6) : (T_SEQ - 1);
                const int p3 = (t0 + 7 < T_SEQ) ? (t0 + 7) : (T_SEQ - 1);
                float xn0 = x[p0 * B_SZ + b], xn1 = x[p1 * B_SZ + b];
                float xn2 = x[p2 * B_SZ + b], xn3 = x[p3 * B_SZ + b];
                const int s = n & 1;
                u64 aI, aF, aG, aO;
                // step 0: from prev tick's step 3
                matvec4(reinterpret_cast<const ulonglong2*>(h0ring[e][s ^ 1][3]),
                        wI, wF, wG, wO, aI, aF, aG, aO);
                float h = cellstep4(comb(aI, fmaf(xt0, wxI, bI)),
                                    comb(aF, fmaf(xt0, wxF, bF)),
                                    comb(aG, fmaf(xt0, wxG, bG)),
                                    comb(aO, fmaf(xt0, wxO, bO)), c);
                h0ring[e][s][0][j] = h;
                __syncwarp();
                // step 1
                matvec4(reinterpret_cast<const ulonglong2*>(h0ring[e][s][0]),
                        wI, wF, wG, wO, aI, aF, aG, aO);
                h = cellstep4(comb(aI, fmaf(xt1, wxI, bI)),
                              comb(aF, fmaf(xt1, wxF, bF)),
                              comb(aG, fmaf(xt1, wxG, bG)),
                              comb(aO, fmaf(xt1, wxO, bO)), c);
                h0ring[e][s][1][j] = h;
                __syncwarp();
                // step 2
                matvec4(reinterpret_cast<const ulonglong2*>(h0ring[e][s][1]),
                        wI, wF, wG, wO, aI, aF, aG, aO);
                h = cellstep4(comb(aI, fmaf(xt2, wxI, bI)),
                              comb(aF, fmaf(xt2, wxF, bF)),
                              comb(aG, fmaf(xt2, wxG, bG)),
                              comb(aO, fmaf(xt2, wxO, bO)), c);
                h0ring[e][s][2][j] = h;
                __syncwarp();
                // step 3
                matvec4(reinterpret_cast<const ulonglong2*>(h0ring[e][s][2]),
                        wI, wF, wG, wO, aI, aF, aG, aO);
                h = cellstep4(comb(aI, fmaf(xt3, wxI, bI)),
                              comb(aF, fmaf(xt3, wxF, bF)),
                              comb(aG, fmaf(xt3, wxG, bG)),
                              comb(aO, fmaf(xt3, wxO, bO)), c);
                h0ring[e][s][3][j] = h;
                xt0 = xn0; xt1 = xn1; xt2 = xn2; xt3 = xn3;
            }
        } else if (role == 1) {
            if (n >= 1 && n <= T_SEQ / 4) {
                const int s = (n - 1) & 1;
#pragma unroll
                for (int st = 0; st < 4; st++) {
                    u64 aI, aF, aG, aO;
                    matvec4(reinterpret_cast<const ulonglong2*>(h0ring[e][s][st]),
                            wI, wF, wG, wO, aI, aF, aG, aO);
                    pring[e][s][st][j] = make_float4(comb(aI, bI), comb(aF, bF),
                                                     comb(aG, bG), comb(aO, bO));
                }
            }
        } else {
            if (n >= 2) {
                const int t0 = 4 * (n - 2);
                const int s  = n & 1;                  // slot (n-2)&1 == n&1
                float* h1o = g_h1 + (size_t)t0 * (B_SZ * 32) + b * 32 + j;
                u64 aI, aF, aG, aO;
                // step 0: from prev tick's step 3
                float4 xp = pring[e][s][0][j];
                matvec4(reinterpret_cast<const ulonglong2*>(h1ring[e][s ^ 1][3]),
                        wI, wF, wG, wO, aI, aF, aG, aO);
                float h = cellstep4(comb(aI, xp.x), comb(aF, xp.y),
                                    comb(aG, xp.z), comb(aO, xp.w), c);
                h1ring[e][s][0][j] = h;
                h1o[0] = h;
                __syncwarp();
                // step 1
                xp = pring[e][s][1][j];
                matvec4(reinterpret_cast<const ulonglong2*>(h1ring[e][s][0]),
                        wI, wF, wG, wO, aI, aF, aG, aO);
                h = cellstep4(comb(aI, xp.x), comb(aF, xp.y),
                              comb(aG, xp.z), comb(aO, xp.w), c);
                h1ring[e][s][1][j] = h;
                h1o[B_SZ * 32] = h;
                __syncwarp();
                // step 2
                xp = pring[e][s][2][j];
                matvec4(reinterpret_cast<const ulonglong2*>(h1ring[e][s][1]),
                        wI, wF, wG, wO, aI, aF, aG, aO);
                h = cellstep4(comb(aI, xp.x), comb(aF, xp.y),
                              comb(aG, xp.z), comb(aO, xp.w), c);
                h1ring[e][s][2][j] = h;
                h1o[2 * B_SZ * 32] = h;
                __syncwarp();
                // step 3
                xp = pring[e][s][3][j];
                matvec4(reinterpret_cast<const ulonglong2*>(h1ring[e][s][2]),
                        wI, wF, wG, wO, aI, aF, aG, aO);
                h = cellstep4(comb(aI, xp.x), comb(aF, xp.y),
                              comb(aG, xp.z), comb(aO, xp.w), c);
                h1ring[e][s][3][j] = h;
                h1o[3 * B_SZ * 32] = h;
            }
        }
        __syncthreads();               // one block barrier per 4 timesteps
    }
}

// =====================================================================
// Dense head: out[t,b] = sum_j h1[t,b,j]*Wd[j] + bd. Memory-bound (~30us).
// =====================================================================
__global__ void __launch_bounds__(256)
k_head(const float* __restrict__ Wd, const float* __restrict__ bd,
       float* __restrict__ out)
{
    const int gw = blockIdx.x * 8 + (threadIdx.x >> 5);
    const int j  = threadIdx.x & 31;
    const size_t r = (size_t)gw * 4 + (j >> 3);
    const int q  = j & 7;

    float4 h = reinterpret_cast<const float4*>(g_h1)[r * 8 + q];
    float4 w = reinterpret_cast<const float4*>(Wd)[q];
    float s = h.x * w.x + h.y * w.y + h.z * w.z + h.w * w.w;
    s += __shfl_xor_sync(0xffffffffu, s, 1);
    s += __shfl_xor_sync(0xffffffffu, s, 2);
    s += __shfl_xor_sync(0xffffffffu, s, 4);
    if (q == 0) out[r] = s + bd[0];
}

// =====================================================================
extern "C" void kernel_launch(void* const* d_in, const int* in_sizes, int n_in,
                              void* d_out, int out_size)
{
    const float* x    = (const float*)d_in[0];
    const float* Wih0 = (const float*)d_in[1];
    const float* Whh0 = (const float*)d_in[2];
    const float* bih0 = (const float*)d_in[3];
    const float* bhh0 = (const float*)d_in[4];
    const float* Wih1 = (const float*)d_in[5];
    const float* Whh1 = (const float*)d_in[6];
    const float* bih1 = (const float*)d_in[7];
    const float* bhh1 = (const float*)d_in[8];
    const float* Wd   = (const float*)d_in[9];
    const float* bd   = (const float*)d_in[10];

    k_fused<<<128, 384>>>(x, Wih0, Whh0, bih0, bhh0, Wih1, Whh1, bih1, bhh1);
    k_head<<<32768, 256>>>(Wd, bd, (float*)d_out);
}